// round 3
// baseline (speedup 1.0000x reference)
#include <cuda_runtime.h>
#include <math.h>

#define BB 512
#define NN 120
#define DD 64
#define ROWS (BB*NN)           // 61440
#define NBINS 32               // DFT bins used (bin 32 / Nyquist unused by band slicing)

// ---------------- scratch (static device allocations; no cudaMalloc) ----------------
__device__ float  g_q[ROWS*DD];
__device__ float  g_k[ROWS*DD];
__device__ float  g_v[ROWS*DD];
__device__ float  g_gam[ROWS];
__device__ float  g_o[ROWS*DD];
__device__ float2 g_tw[NBINS*DD];   // (cos, sin) twiddles

// ---------------- twiddle init: tw[f*64+d] = (cos, sin)(2*pi*(f*d mod 64)/64) ----------------
__global__ void twiddle_kernel() {
    int i = blockIdx.x * blockDim.x + threadIdx.x;
    if (i < NBINS*DD) {
        int f = i >> 6, d = i & 63;
        int m = (f * d) & 63;                 // exact modular reduction
        double th = (2.0 * 3.14159265358979323846 * (double)m) / 64.0;
        g_tw[i] = make_float2((float)cos(th), (float)sin(th));
    }
}

// ---------------- preprocess: h = zc_rms(x), q/k/v projections, gamma gate ----------------
// one warp per row; lane t owns elements (2t, 2t+1); 8 rows per 256-thread block
__global__ void __launch_bounds__(256) pre_kernel(
    const float* __restrict__ x,  const float* __restrict__ g_norm,
    const float* __restrict__ Wq, const float* __restrict__ Wk,
    const float* __restrict__ Wv, const float* __restrict__ bv,
    const float* __restrict__ W1, const float* __restrict__ b1,
    const float* __restrict__ W2, const float* __restrict__ b2)
{
    const int warp = threadIdx.x >> 5;
    const int lane = threadIdx.x & 31;
    const int row  = blockIdx.x * 8 + warp;
    __shared__ float sh[8][DD];
    __shared__ float smag[8][NBINS];
    if (row >= ROWS) return;

    // ---- zero-centered RMS norm ----
    float2 xv = ((const float2*)(x + row*DD))[lane];
    float s = xv.x + xv.y;
    #pragma unroll
    for (int o = 16; o; o >>= 1) s += __shfl_xor_sync(0xffffffffu, s, o);
    float mean = s * (1.0f/64.0f);
    float a0 = xv.x - mean, a1 = xv.y - mean;
    float ss = a0*a0 + a1*a1;
    #pragma unroll
    for (int o = 16; o; o >>= 1) ss += __shfl_xor_sync(0xffffffffu, ss, o);
    float rn = rsqrtf(ss * (1.0f/64.0f) + 1e-8f);
    float2 gv = ((const float2*)g_norm)[lane];
    float h0 = a0 * rn * gv.x;
    float h1 = a1 * rn * gv.y;
    sh[warp][2*lane]   = h0;
    sh[warp][2*lane+1] = h1;
    __syncwarp();

    // ---- three matvecs: out[d] = sum_e h[e] * W[e*64 + d] ----
    float q0=0.f,q1=0.f,k0=0.f,k1=0.f,v0=0.f,v1=0.f;
    #pragma unroll 8
    for (int e = 0; e < DD; e++) {
        float he = sh[warp][e];
        float2 wq = ((const float2*)(Wq + e*DD))[lane];
        float2 wk = ((const float2*)(Wk + e*DD))[lane];
        float2 wv = ((const float2*)(Wv + e*DD))[lane];
        q0 = fmaf(he, wq.x, q0); q1 = fmaf(he, wq.y, q1);
        k0 = fmaf(he, wk.x, k0); k1 = fmaf(he, wk.y, k1);
        v0 = fmaf(he, wv.x, v0); v1 = fmaf(he, wv.y, v1);
    }
    // l2 norms (sum, not mean)
    float qs = q0*q0 + q1*q1;
    #pragma unroll
    for (int o = 16; o; o >>= 1) qs += __shfl_xor_sync(0xffffffffu, qs, o);
    float qr = rsqrtf(qs + 1e-8f);
    float ks = k0*k0 + k1*k1;
    #pragma unroll
    for (int o = 16; o; o >>= 1) ks += __shfl_xor_sync(0xffffffffu, ks, o);
    float kr = rsqrtf(ks + 1e-8f);
    float2 bvv = ((const float2*)bv)[lane];
    ((float2*)(g_q + row*DD))[lane] = make_float2(q0*qr, q1*qr);
    ((float2*)(g_k + row*DD))[lane] = make_float2(k0*kr, k1*kr);
    ((float2*)(g_v + row*DD))[lane] = make_float2(v0 + bvv.x, v1 + bvv.y);

    // ---- DFT magnitude, bin = lane (0..31) ----
    float re = 0.f, im = 0.f;
    #pragma unroll 8
    for (int d = 0; d < DD; d++) {
        float hd = sh[warp][d];
        float2 tw = g_tw[lane*DD + d];
        re = fmaf(hd, tw.x, re);
        im = fmaf(hd, tw.y, im);
    }
    smag[warp][lane] = sqrtf(re*re + im*im);
    __syncwarp();

    // ---- band energies (8 bands of 4 bins), normalize, MLP gate ----
    float en[8];
    float esum = 0.f;
    #pragma unroll
    for (int i = 0; i < 8; i++) {
        en[i] = (smag[warp][4*i] + smag[warp][4*i+1] +
                 smag[warp][4*i+2] + smag[warp][4*i+3]) * 0.25f;
        esum += en[i];
    }
    float inv = 1.0f / fmaxf(esum, 1e-8f);
    float hid = 0.f;
    if (lane < 16) {
        float z = b1[lane];
        #pragma unroll
        for (int i = 0; i < 8; i++) z = fmaf(en[i]*inv, W1[i*16 + lane], z);
        float sg = 1.0f / (1.0f + expf(-z));   // silu = z * sigmoid(z)
        hid = z * sg * W2[lane];
    }
    #pragma unroll
    for (int o = 16; o; o >>= 1) hid += __shfl_xor_sync(0xffffffffu, hid, o);
    if (lane == 0) {
        float z2 = hid + b2[0];
        g_gam[row] = 0.5f + 0.49f / (1.0f + expf(-z2));
    }
}

// ---------------- sequential scan: one CTA per batch, thread d owns S[d][0..63] ----------------
__global__ void __launch_bounds__(64) scan_kernel() {
    const int b = blockIdx.x;
    const int d = threadIdx.x;
    __shared__ float shk[DD];
    __shared__ float shq[DD];

    float S[DD];
    #pragma unroll
    for (int e = 0; e < DD; e++) S[e] = 0.f;

    const float* __restrict__ qb = g_q   + b*NN*DD;
    const float* __restrict__ kb = g_k   + b*NN*DD;
    const float* __restrict__ vb = g_v   + b*NN*DD;
    const float* __restrict__ gb = g_gam + b*NN;
    float* __restrict__       ob = g_o   + b*NN*DD;

    // prefetch step 0
    float kd = kb[d];
    float qd = qb[d];
    float vd = vb[d];
    float gm = gb[0];

    for (int t = 0; t < NN; t++) {
        shk[d] = kd;
        shq[d] = qd;
        __syncthreads();
        float vcur = vd, gcur = gm;
        // software prefetch next step (hides L2 latency behind compute)
        if (t + 1 < NN) {
            kd = kb[(t+1)*DD + d];
            qd = qb[(t+1)*DD + d];
            vd = vb[(t+1)*DD + d];
            gm = gb[t+1];
        }
        // pred = S_row . k
        float pred = 0.f;
        #pragma unroll
        for (int e = 0; e < DD; e++) pred = fmaf(S[e], shk[e], pred);
        float delta = fminf(fmaxf(vcur - pred, -5.0f), 5.0f);
        // fused: S = clip(g*S + delta*k, +-10); o = S_new . q
        float o = 0.f;
        #pragma unroll
        for (int e = 0; e < DD; e++) {
            float sv = fmaf(gcur, S[e], delta * shk[e]);
            sv = fminf(fmaxf(sv, -10.0f), 10.0f);
            S[e] = sv;
            o = fmaf(sv, shq[e], o);
        }
        ob[t*DD + d] = o;
        __syncthreads();
    }
}

// ---------------- epilogue: out = x + zc_rms(o, g_post) @ Wo + bo ----------------
__global__ void __launch_bounds__(256) post_kernel(
    const float* __restrict__ x, const float* __restrict__ g_post,
    const float* __restrict__ Wo, const float* __restrict__ bo,
    float* __restrict__ out)
{
    const int warp = threadIdx.x >> 5;
    const int lane = threadIdx.x & 31;
    const int row  = blockIdx.x * 8 + warp;
    __shared__ float sh[8][DD];
    if (row >= ROWS) return;

    float2 ov = ((const float2*)(g_o + row*DD))[lane];
    float s = ov.x + ov.y;
    #pragma unroll
    for (int o = 16; o; o >>= 1) s += __shfl_xor_sync(0xffffffffu, s, o);
    float mean = s * (1.0f/64.0f);
    float a0 = ov.x - mean, a1 = ov.y - mean;
    float ss = a0*a0 + a1*a1;
    #pragma unroll
    for (int o = 16; o; o >>= 1) ss += __shfl_xor_sync(0xffffffffu, ss, o);
    float rn = rsqrtf(ss * (1.0f/64.0f) + 1e-8f);
    float2 gp = ((const float2*)g_post)[lane];
    sh[warp][2*lane]   = a0 * rn * gp.x;
    sh[warp][2*lane+1] = a1 * rn * gp.y;
    __syncwarp();

    float2 bov = ((const float2*)bo)[lane];
    float acc0 = bov.x, acc1 = bov.y;
    #pragma unroll 8
    for (int e = 0; e < DD; e++) {
        float he = sh[warp][e];
        float2 wo = ((const float2*)(Wo + e*DD))[lane];
        acc0 = fmaf(he, wo.x, acc0);
        acc1 = fmaf(he, wo.y, acc1);
    }
    float2 xv = ((const float2*)(x + row*DD))[lane];
    ((float2*)(out + row*DD))[lane] = make_float2(xv.x + acc0, xv.y + acc1);
}

// ---------------- launch ----------------
extern "C" void kernel_launch(void* const* d_in, const int* in_sizes, int n_in,
                              void* d_out, int out_size)
{
    const float* x      = (const float*)d_in[0];
    const float* g_norm = (const float*)d_in[1];
    const float* Wq     = (const float*)d_in[2];
    const float* Wk     = (const float*)d_in[3];
    const float* Wv     = (const float*)d_in[4];
    const float* bv     = (const float*)d_in[5];
    const float* Wo     = (const float*)d_in[6];
    const float* bo     = (const float*)d_in[7];
    const float* g_post = (const float*)d_in[8];
    const float* W1     = (const float*)d_in[9];
    const float* b1     = (const float*)d_in[10];
    const float* W2     = (const float*)d_in[11];
    const float* b2     = (const float*)d_in[12];
    float* out          = (float*)d_out;

    twiddle_kernel<<<(NBINS*DD + 255)/256, 256>>>();
    pre_kernel<<<ROWS/8, 256>>>(x, g_norm, Wq, Wk, Wv, bv, W1, b1, W2, b2);
    scan_kernel<<<BB, DD>>>();
    post_kernel<<<ROWS/8, 256>>>(x, g_post, Wo, bo, out);
}

// round 5
// speedup vs baseline: 1.8503x; 1.8503x over previous
#include <cuda_runtime.h>
#include <math.h>

#define BB 512
#define NN 120
#define DD 64
#define ROWS (BB*NN)           // 61440
#define NBINS 32

// ---------------- scratch (static device allocations; no cudaMalloc) ----------------
__device__ float  g_q[ROWS*DD];
__device__ float  g_k[ROWS*DD];
__device__ float  g_v[ROWS*DD];
__device__ float  g_gam[ROWS];
__device__ float  g_o[ROWS*DD];
__device__ float2 g_tw[NBINS*DD];   // (cos, sin) twiddles

// ---------------- twiddle init ----------------
__global__ void twiddle_kernel() {
    int i = blockIdx.x * blockDim.x + threadIdx.x;
    if (i < NBINS*DD) {
        int f = i >> 6, d = i & 63;
        int m = (f * d) & 63;                 // exact modular reduction
        double th = (2.0 * 3.14159265358979323846 * (double)m) / 64.0;
        g_tw[i] = make_float2((float)cos(th), (float)sin(th));
    }
}

// ---------------- preprocess: 4 rows per warp (W loads amortized 4x) ----------------
__global__ void __launch_bounds__(256) pre_kernel(
    const float* __restrict__ x,  const float* __restrict__ g_norm,
    const float* __restrict__ Wq, const float* __restrict__ Wk,
    const float* __restrict__ Wv, const float* __restrict__ bv,
    const float* __restrict__ W1, const float* __restrict__ b1,
    const float* __restrict__ W2, const float* __restrict__ b2)
{
    const int warp = threadIdx.x >> 5;
    const int lane = threadIdx.x & 31;
    const int row0 = blockIdx.x * 32 + warp * 4;
    __shared__ float sh[8][4][DD];
    __shared__ float smag[8][4][NBINS];

    // ---- zc_rms for 4 rows ----
    float2 gv = ((const float2*)g_norm)[lane];
    #pragma unroll
    for (int r = 0; r < 4; r++) {
        float2 xv = ((const float2*)(x + (row0 + r)*DD))[lane];
        float s = xv.x + xv.y;
        #pragma unroll
        for (int o = 16; o; o >>= 1) s += __shfl_xor_sync(0xffffffffu, s, o);
        float mean = s * (1.0f/64.0f);
        float a0 = xv.x - mean, a1 = xv.y - mean;
        float ss = a0*a0 + a1*a1;
        #pragma unroll
        for (int o = 16; o; o >>= 1) ss += __shfl_xor_sync(0xffffffffu, ss, o);
        float rn = rsqrtf(ss * (1.0f/64.0f) + 1e-8f);
        sh[warp][r][2*lane]   = a0 * rn * gv.x;
        sh[warp][r][2*lane+1] = a1 * rn * gv.y;
    }
    __syncwarp();

    // ---- three matvecs for 4 rows; W element loaded once per warp ----
    float qa[4][2], ka[4][2], va[4][2];
    #pragma unroll
    for (int r = 0; r < 4; r++) {
        qa[r][0]=qa[r][1]=ka[r][0]=ka[r][1]=va[r][0]=va[r][1]=0.f;
    }
    #pragma unroll 4
    for (int e = 0; e < DD; e++) {
        float2 wq = ((const float2*)(Wq + e*DD))[lane];
        float2 wk = ((const float2*)(Wk + e*DD))[lane];
        float2 wv = ((const float2*)(Wv + e*DD))[lane];
        #pragma unroll
        for (int r = 0; r < 4; r++) {
            float he = sh[warp][r][e];
            qa[r][0] = fmaf(he, wq.x, qa[r][0]); qa[r][1] = fmaf(he, wq.y, qa[r][1]);
            ka[r][0] = fmaf(he, wk.x, ka[r][0]); ka[r][1] = fmaf(he, wk.y, ka[r][1]);
            va[r][0] = fmaf(he, wv.x, va[r][0]); va[r][1] = fmaf(he, wv.y, va[r][1]);
        }
    }
    float2 bvv = ((const float2*)bv)[lane];
    #pragma unroll
    for (int r = 0; r < 4; r++) {
        float qs = qa[r][0]*qa[r][0] + qa[r][1]*qa[r][1];
        #pragma unroll
        for (int o = 16; o; o >>= 1) qs += __shfl_xor_sync(0xffffffffu, qs, o);
        float qr = rsqrtf(qs + 1e-8f);
        float ks = ka[r][0]*ka[r][0] + ka[r][1]*ka[r][1];
        #pragma unroll
        for (int o = 16; o; o >>= 1) ks += __shfl_xor_sync(0xffffffffu, ks, o);
        float kr = rsqrtf(ks + 1e-8f);
        int row = row0 + r;
        ((float2*)(g_q + row*DD))[lane] = make_float2(qa[r][0]*qr, qa[r][1]*qr);
        ((float2*)(g_k + row*DD))[lane] = make_float2(ka[r][0]*kr, ka[r][1]*kr);
        ((float2*)(g_v + row*DD))[lane] = make_float2(va[r][0]+bvv.x, va[r][1]+bvv.y);
    }

    // ---- DFT magnitudes, bin = lane, 4 rows at once ----
    float re[4] = {0.f,0.f,0.f,0.f}, im[4] = {0.f,0.f,0.f,0.f};
    #pragma unroll 8
    for (int d = 0; d < DD; d++) {
        float2 tw = g_tw[lane*DD + d];
        #pragma unroll
        for (int r = 0; r < 4; r++) {
            float hd = sh[warp][r][d];
            re[r] = fmaf(hd, tw.x, re[r]);
            im[r] = fmaf(hd, tw.y, im[r]);
        }
    }
    #pragma unroll
    for (int r = 0; r < 4; r++)
        smag[warp][r][lane] = sqrtf(re[r]*re[r] + im[r]*im[r]);
    __syncwarp();

    // ---- gate: 8 lanes per row, lane = (row, band) ----
    {
        int r   = lane >> 3;      // row within group of 4
        int bnd = lane & 7;       // band index
        const float* mg = smag[warp][r];
        float en = 0.25f * (mg[4*bnd] + mg[4*bnd+1] + mg[4*bnd+2] + mg[4*bnd+3]);
        float esum = en;
        esum += __shfl_xor_sync(0xffffffffu, esum, 1);
        esum += __shfl_xor_sync(0xffffffffu, esum, 2);
        esum += __shfl_xor_sync(0xffffffffu, esum, 4);
        float eni = en / fmaxf(esum, 1e-8f);
        // hidden layer: this lane computes units 2*bnd and 2*bnd+1
        float z0 = b1[2*bnd], z1 = b1[2*bnd+1];
        int gbase = lane & 24;    // start lane of this 8-lane group
        #pragma unroll
        for (int i = 0; i < 8; i++) {
            float ei = __shfl_sync(0xffffffffu, eni, gbase + i);
            z0 = fmaf(ei, W1[i*16 + 2*bnd],     z0);
            z1 = fmaf(ei, W1[i*16 + 2*bnd + 1], z1);
        }
        float s0 = z0 / (1.0f + expf(-z0)) * W2[2*bnd];
        float s1 = z1 / (1.0f + expf(-z1)) * W2[2*bnd+1];
        float hid = s0 + s1;
        hid += __shfl_xor_sync(0xffffffffu, hid, 1);
        hid += __shfl_xor_sync(0xffffffffu, hid, 2);
        hid += __shfl_xor_sync(0xffffffffu, hid, 4);
        if (bnd == 0) {
            float z2 = hid + b2[0];
            g_gam[row0 + r] = 0.5f + 0.49f / (1.0f + expf(-z2));
        }
    }
}

// ---------------- scan: 4 threads per state row, no smem, no barriers ----------------
// thread (d, sub) owns S[d][16*sub .. 16*sub+15]; row dot-products via shfl over subs
__global__ void __launch_bounds__(256) scan_kernel() {
    const int b   = blockIdx.x;
    const int d   = threadIdx.x >> 2;
    const int sub = threadIdx.x & 3;
    const int eb  = sub * 16;

    const float4* __restrict__ kb = (const float4*)(g_k + b*NN*DD + eb);
    const float4* __restrict__ qb = (const float4*)(g_q + b*NN*DD + eb);
    const float*  __restrict__ vb = g_v + b*NN*DD + d;
    const float*  __restrict__ gb = g_gam + b*NN;
    float*        __restrict__ ob = g_o + b*NN*DD + d;

    float S[16];
    #pragma unroll
    for (int i = 0; i < 16; i++) S[i] = 0.f;

    // prefetch step 0
    float4 kp0 = kb[0], kp1 = kb[1], kp2 = kb[2], kp3 = kb[3];
    float4 qp0 = qb[0], qp1 = qb[1], qp2 = qb[2], qp3 = qb[3];
    float vp = vb[0];
    float gp = gb[0];

    #pragma unroll 1
    for (int t = 0; t < NN; t++) {
        float4 k0 = kp0, k1 = kp1, k2 = kp2, k3 = kp3;
        float4 q0 = qp0, q1 = qp1, q2 = qp2, q3 = qp3;
        float vc = vp, gc = gp;
        if (t + 1 < NN) {
            const float4* kn = kb + (t+1)*16;
            kp0 = kn[0]; kp1 = kn[1]; kp2 = kn[2]; kp3 = kn[3];
            const float4* qn = qb + (t+1)*16;
            qp0 = qn[0]; qp1 = qn[1]; qp2 = qn[2]; qp3 = qn[3];
            vp = vb[(t+1)*DD];
            gp = gb[t+1];
        }

        // pred = S_row . k   (4 independent 4-deep chains, then shfl all-reduce over subs)
        float p0 = fmaf(k0.x, S[0],  k0.y * S[1]);
        p0 = fmaf(k0.z, S[2],  p0);  p0 = fmaf(k0.w, S[3],  p0);
        float p1 = fmaf(k1.x, S[4],  k1.y * S[5]);
        p1 = fmaf(k1.z, S[6],  p1);  p1 = fmaf(k1.w, S[7],  p1);
        float p2 = fmaf(k2.x, S[8],  k2.y * S[9]);
        p2 = fmaf(k2.z, S[10], p2);  p2 = fmaf(k2.w, S[11], p2);
        float p3 = fmaf(k3.x, S[12], k3.y * S[13]);
        p3 = fmaf(k3.z, S[14], p3);  p3 = fmaf(k3.w, S[15], p3);
        float pred = (p0 + p1) + (p2 + p3);
        pred += __shfl_xor_sync(0xffffffffu, pred, 1);
        pred += __shfl_xor_sync(0xffffffffu, pred, 2);

        float delta = fminf(fmaxf(vc - pred, -5.0f), 5.0f);

        // S = clip(g*S + delta*k, +-10); o_partial = S_new . q
        float o0, o1, o2, o3;
        #define UPD(i, kc, qc, oacc) { \
            float sv = fmaf(gc, S[i], delta * (kc)); \
            sv = fminf(fmaxf(sv, -10.0f), 10.0f); \
            S[i] = sv; \
            oacc = fmaf(sv, (qc), oacc); }
        o0 = 0.f; UPD(0,  k0.x, q0.x, o0) UPD(1,  k0.y, q0.y, o0)
                  UPD(2,  k0.z, q0.z, o0) UPD(3,  k0.w, q0.w, o0)
        o1 = 0.f; UPD(4,  k1.x, q1.x, o1) UPD(5,  k1.y, q1.y, o1)
                  UPD(6,  k1.z, q1.z, o1) UPD(7,  k1.w, q1.w, o1)
        o2 = 0.f; UPD(8,  k2.x, q2.x, o2) UPD(9,  k2.y, q2.y, o2)
                  UPD(10, k2.z, q2.z, o2) UPD(11, k2.w, q2.w, o2)
        o3 = 0.f; UPD(12, k3.x, q3.x, o3) UPD(13, k3.y, q3.y, o3)
                  UPD(14, k3.z, q3.z, o3) UPD(15, k3.w, q3.w, o3)
        #undef UPD

        float o = (o0 + o1) + (o2 + o3);
        o += __shfl_xor_sync(0xffffffffu, o, 1);
        o += __shfl_xor_sync(0xffffffffu, o, 2);
        if (sub == 0) ob[t*DD] = o;
    }
}

// ---------------- epilogue: 4 rows per warp ----------------
__global__ void __launch_bounds__(256) post_kernel(
    const float* __restrict__ x, const float* __restrict__ g_post,
    const float* __restrict__ Wo, const float* __restrict__ bo,
    float* __restrict__ out)
{
    const int warp = threadIdx.x >> 5;
    const int lane = threadIdx.x & 31;
    const int row0 = blockIdx.x * 32 + warp * 4;
    __shared__ float sh[8][4][DD];

    float2 gp2 = ((const float2*)g_post)[lane];
    #pragma unroll
    for (int r = 0; r < 4; r++) {
        float2 ov = ((const float2*)(g_o + (row0 + r)*DD))[lane];
        float s = ov.x + ov.y;
        #pragma unroll
        for (int o = 16; o; o >>= 1) s += __shfl_xor_sync(0xffffffffu, s, o);
        float mean = s * (1.0f/64.0f);
        float a0 = ov.x - mean, a1 = ov.y - mean;
        float ss = a0*a0 + a1*a1;
        #pragma unroll
        for (int o = 16; o; o >>= 1) ss += __shfl_xor_sync(0xffffffffu, ss, o);
        float rn = rsqrtf(ss * (1.0f/64.0f) + 1e-8f);
        sh[warp][r][2*lane]   = a0 * rn * gp2.x;
        sh[warp][r][2*lane+1] = a1 * rn * gp2.y;
    }
    __syncwarp();

    float2 bov = ((const float2*)bo)[lane];
    float acc[4][2];
    #pragma unroll
    for (int r = 0; r < 4; r++) { acc[r][0] = bov.x; acc[r][1] = bov.y; }
    #pragma unroll 4
    for (int e = 0; e < DD; e++) {
        float2 wo = ((const float2*)(Wo + e*DD))[lane];
        #pragma unroll
        for (int r = 0; r < 4; r++) {
            float he = sh[warp][r][e];
            acc[r][0] = fmaf(he, wo.x, acc[r][0]);
            acc[r][1] = fmaf(he, wo.y, acc[r][1]);
        }
    }
    #pragma unroll
    for (int r = 0; r < 4; r++) {
        int row = row0 + r;
        float2 xv = ((const float2*)(x + row*DD))[lane];
        ((float2*)(out + row*DD))[lane] =
            make_float2(xv.x + acc[r][0], xv.y + acc[r][1]);
    }
}

// ---------------- launch ----------------
extern "C" void kernel_launch(void* const* d_in, const int* in_sizes, int n_in,
                              void* d_out, int out_size)
{
    const float* x      = (const float*)d_in[0];
    const float* g_norm = (const float*)d_in[1];
    const float* Wq     = (const float*)d_in[2];
    const float* Wk     = (const float*)d_in[3];
    const float* Wv     = (const float*)d_in[4];
    const float* bv     = (const float*)d_in[5];
    const float* Wo     = (const float*)d_in[6];
    const float* bo     = (const float*)d_in[7];
    const float* g_post = (const float*)d_in[8];
    const float* W1     = (const float*)d_in[9];
    const float* b1     = (const float*)d_in[10];
    const float* W2     = (const float*)d_in[11];
    const float* b2     = (const float*)d_in[12];
    float* out          = (float*)d_out;

    twiddle_kernel<<<(NBINS*DD + 255)/256, 256>>>();
    pre_kernel<<<ROWS/32, 256>>>(x, g_norm, Wq, Wk, Wv, bv, W1, b1, W2, b2);
    scan_kernel<<<BB, 256>>>();
    post_kernel<<<ROWS/32, 256>>>(x, g_post, Wo, bo, out);
}

// round 6
// speedup vs baseline: 2.7314x; 1.4762x over previous
#include <cuda_runtime.h>
#include <math.h>

#define BB 512
#define NN 120
#define DD 64
#define ROWS (BB*NN)           // 61440
#define NBINS 32

typedef unsigned long long u64;

// ---------------- scratch (static device arrays; no cudaMalloc) ----------------
__device__ float  g_q[ROWS*DD];
__device__ float  g_k[ROWS*DD];
__device__ float  g_v[ROWS*DD];
__device__ float  g_gam[ROWS];
__device__ float  g_o[ROWS*DD];
// twiddle planes paired over d: twc[d2*32+bin] = (cos(2pi*f*(2d2)/64), cos(...(2d2+1)...))
__device__ float2 g_twc[1024];
__device__ float2 g_tws[1024];
// W repacked over e-pairs: P[e2*32+lane] = (W[2e2][2l], W[2e2+1][2l], W[2e2][2l+1], W[2e2+1][2l+1])
__device__ float4 g_Wqp[1024], g_Wkp[1024], g_Wvp[1024], g_Wop[1024];

// ---------------- f32x2 helpers ----------------
__device__ __forceinline__ u64 fma2(u64 a, u64 b, u64 c) {
    u64 d; asm("fma.rn.f32x2 %0,%1,%2,%3;" : "=l"(d) : "l"(a), "l"(b), "l"(c)); return d;
}
__device__ __forceinline__ u64 mul2(u64 a, u64 b) {
    u64 d; asm("mul.rn.f32x2 %0,%1,%2;" : "=l"(d) : "l"(a), "l"(b)); return d;
}
__device__ __forceinline__ u64 dup2(float v) {
    u64 r; asm("mov.b64 %0,{%1,%1};" : "=l"(r) : "f"(v)); return r;
}
__device__ __forceinline__ float2 unp(u64 v) {
    float a, b; asm("mov.b64 {%0,%1},%2;" : "=f"(a), "=f"(b) : "l"(v));
    return make_float2(a, b);
}
// S' = clip(g*S + delta*k, +-10), all in packed regs (movs eliminated by ptxas)
__device__ __forceinline__ u64 upd2(u64 S, u64 k, u64 g, u64 delta) {
    u64 r;
    asm("{\n\t"
        ".reg .f32 lo,hi;\n\t"
        ".reg .b64 t;\n\t"
        "mul.rn.f32x2 t, %2, %3;\n\t"
        "fma.rn.f32x2 t, %4, %1, t;\n\t"
        "mov.b64 {lo,hi}, t;\n\t"
        "min.f32 lo, lo, 0f41200000;\n\t"
        "max.f32 lo, lo, 0fC1200000;\n\t"
        "min.f32 hi, hi, 0f41200000;\n\t"
        "max.f32 hi, hi, 0fC1200000;\n\t"
        "mov.b64 %0, {lo,hi};\n\t"
        "}"
        : "=l"(r) : "l"(S), "l"(k), "l"(delta), "l"(g));
    return r;
}

// ---------------- init: twiddle planes + W e-pair repack ----------------
__global__ void init_kernel(const float* __restrict__ Wq, const float* __restrict__ Wk,
                            const float* __restrict__ Wv, const float* __restrict__ Wo) {
    int i = blockIdx.x * blockDim.x + threadIdx.x;
    if (i < 1024) {
        int d2 = i >> 5, f = i & 31;
        int m0 = (f * (2*d2))     & 63;       // exact modular angle reduction
        int m1 = (f * (2*d2 + 1)) & 63;
        const double w = 2.0 * 3.14159265358979323846 / 64.0;
        g_twc[i] = make_float2((float)cos(w*m0), (float)cos(w*m1));
        g_tws[i] = make_float2((float)sin(w*m0), (float)sin(w*m1));
    } else if (i < 5120) {
        int s = (i - 1024) >> 10, j = (i - 1024) & 1023;
        int e2 = j >> 5, l = j & 31;
        const float* W = (s == 0) ? Wq : (s == 1) ? Wk : (s == 2) ? Wv : Wo;
        float4*      P = (s == 0) ? g_Wqp : (s == 1) ? g_Wkp : (s == 2) ? g_Wvp : g_Wop;
        int a = (2*e2)*DD + 2*l;
        P[j] = make_float4(W[a], W[a+DD], W[a+1], W[a+DD+1]);
    }
}

// ---------------- preprocess: 4 rows/warp, packed e-pair matvecs + DFT ----------------
__global__ void __launch_bounds__(256) pre_kernel(
    const float* __restrict__ x,  const float* __restrict__ g_norm,
    const float* __restrict__ bv,
    const float* __restrict__ W1, const float* __restrict__ b1,
    const float* __restrict__ W2, const float* __restrict__ b2)
{
    const int warp = threadIdx.x >> 5;
    const int lane = threadIdx.x & 31;
    const int row0 = blockIdx.x * 32 + warp * 4;
    __shared__ __align__(16) float sh[8][4][DD];
    __shared__ float smag[8][4][NBINS];

    // ---- zc_rms for 4 rows ----
    float2 gv = ((const float2*)g_norm)[lane];
    #pragma unroll
    for (int r = 0; r < 4; r++) {
        float2 xv = ((const float2*)(x + (row0 + r)*DD))[lane];
        float s = xv.x + xv.y;
        #pragma unroll
        for (int o = 16; o; o >>= 1) s += __shfl_xor_sync(0xffffffffu, s, o);
        float mean = s * (1.0f/64.0f);
        float a0 = xv.x - mean, a1 = xv.y - mean;
        float ss = a0*a0 + a1*a1;
        #pragma unroll
        for (int o = 16; o; o >>= 1) ss += __shfl_xor_sync(0xffffffffu, ss, o);
        float rn = rsqrtf(ss * (1.0f/64.0f) + 1e-8f);
        sh[warp][r][2*lane]   = a0 * rn * gv.x;
        sh[warp][r][2*lane+1] = a1 * rn * gv.y;
    }
    __syncwarp();

    // ---- three matvecs, packed over e-pairs: acc halves = (even-e, odd-e) partials ----
    // per row: accs for outputs 2*lane (E) and 2*lane+1 (O), for q/k/v
    u64 qE[4], qO[4], kE[4], kO[4], vE[4], vO[4];
    #pragma unroll
    for (int r = 0; r < 4; r++) { qE[r]=qO[r]=kE[r]=kO[r]=vE[r]=vO[r]=0ull; }
    const ulonglong2* Wqp = (const ulonglong2*)g_Wqp;
    const ulonglong2* Wkp = (const ulonglong2*)g_Wkp;
    const ulonglong2* Wvp = (const ulonglong2*)g_Wvp;
    #pragma unroll 4
    for (int e2 = 0; e2 < 32; e2++) {
        ulonglong2 wq = Wqp[e2*32 + lane];
        ulonglong2 wk = Wkp[e2*32 + lane];
        ulonglong2 wv = Wvp[e2*32 + lane];
        #pragma unroll
        for (int r = 0; r < 4; r++) {
            u64 h2 = ((const u64*)sh[warp][r])[e2];   // (h[2e2], h[2e2+1])
            qE[r] = fma2(h2, wq.x, qE[r]);  qO[r] = fma2(h2, wq.y, qO[r]);
            kE[r] = fma2(h2, wk.x, kE[r]);  kO[r] = fma2(h2, wk.y, kO[r]);
            vE[r] = fma2(h2, wv.x, vE[r]);  vO[r] = fma2(h2, wv.y, vO[r]);
        }
    }
    float2 bvv = ((const float2*)bv)[lane];
    #pragma unroll
    for (int r = 0; r < 4; r++) {
        float2 e0 = unp(qE[r]), e1 = unp(qO[r]);
        float q0 = e0.x + e0.y, q1 = e1.x + e1.y;
        e0 = unp(kE[r]); e1 = unp(kO[r]);
        float k0 = e0.x + e0.y, k1 = e1.x + e1.y;
        e0 = unp(vE[r]); e1 = unp(vO[r]);
        float v0 = e0.x + e0.y, v1 = e1.x + e1.y;

        float qs = q0*q0 + q1*q1;
        #pragma unroll
        for (int o = 16; o; o >>= 1) qs += __shfl_xor_sync(0xffffffffu, qs, o);
        float qr = rsqrtf(qs + 1e-8f);
        float ks = k0*k0 + k1*k1;
        #pragma unroll
        for (int o = 16; o; o >>= 1) ks += __shfl_xor_sync(0xffffffffu, ks, o);
        float kr = rsqrtf(ks + 1e-8f);
        int row = row0 + r;
        ((float2*)(g_q + row*DD))[lane] = make_float2(q0*qr, q1*qr);
        ((float2*)(g_k + row*DD))[lane] = make_float2(k0*kr, k1*kr);
        ((float2*)(g_v + row*DD))[lane] = make_float2(v0 + bvv.x, v1 + bvv.y);
    }

    // ---- DFT magnitudes, bin = lane, packed over d-pairs (coalesced twiddle planes) ----
    u64 re2[4] = {0,0,0,0}, im2[4] = {0,0,0,0};
    const u64* twc = (const u64*)g_twc;
    const u64* tws = (const u64*)g_tws;
    #pragma unroll 4
    for (int d2 = 0; d2 < 32; d2++) {
        u64 c2 = twc[d2*32 + lane];
        u64 s2 = tws[d2*32 + lane];
        #pragma unroll
        for (int r = 0; r < 4; r++) {
            u64 h2 = ((const u64*)sh[warp][r])[d2];
            re2[r] = fma2(h2, c2, re2[r]);
            im2[r] = fma2(h2, s2, im2[r]);
        }
    }
    #pragma unroll
    for (int r = 0; r < 4; r++) {
        float2 rr = unp(re2[r]), ii = unp(im2[r]);
        float re = rr.x + rr.y, im = ii.x + ii.y;
        smag[warp][r][lane] = sqrtf(re*re + im*im);
    }
    __syncwarp();

    // ---- gate: 8 lanes per row ----
    {
        int r   = lane >> 3;
        int bnd = lane & 7;
        const float* mg = smag[warp][r];
        float en = 0.25f * (mg[4*bnd] + mg[4*bnd+1] + mg[4*bnd+2] + mg[4*bnd+3]);
        float esum = en;
        esum += __shfl_xor_sync(0xffffffffu, esum, 1);
        esum += __shfl_xor_sync(0xffffffffu, esum, 2);
        esum += __shfl_xor_sync(0xffffffffu, esum, 4);
        float eni = en / fmaxf(esum, 1e-8f);
        float z0 = b1[2*bnd], z1 = b1[2*bnd+1];
        int gbase = lane & 24;
        #pragma unroll
        for (int i = 0; i < 8; i++) {
            float ei = __shfl_sync(0xffffffffu, eni, gbase + i);
            z0 = fmaf(ei, W1[i*16 + 2*bnd],     z0);
            z1 = fmaf(ei, W1[i*16 + 2*bnd + 1], z1);
        }
        float s0 = z0 / (1.0f + expf(-z0)) * W2[2*bnd];
        float s1 = z1 / (1.0f + expf(-z1)) * W2[2*bnd+1];
        float hid = s0 + s1;
        hid += __shfl_xor_sync(0xffffffffu, hid, 1);
        hid += __shfl_xor_sync(0xffffffffu, hid, 2);
        hid += __shfl_xor_sync(0xffffffffu, hid, 4);
        if (bnd == 0) {
            float z2 = hid + b2[0];
            g_gam[row0 + r] = 0.5f + 0.49f / (1.0f + expf(-z2));
        }
    }
}

// ---------------- scan: 4 threads/row, packed state, no smem/barriers ----------------
__global__ void __launch_bounds__(256, 4) scan_kernel() {
    const int b   = blockIdx.x;
    const int d   = threadIdx.x >> 2;
    const int sub = threadIdx.x & 3;

    const ulonglong2* __restrict__ kb = (const ulonglong2*)(g_k + b*NN*DD + sub*16);
    const ulonglong2* __restrict__ qb = (const ulonglong2*)(g_q + b*NN*DD + sub*16);
    const float*  __restrict__ vb = g_v + b*NN*DD + d;
    const float*  __restrict__ gb = g_gam + b*NN;
    float*        __restrict__ op = g_o + b*NN*DD + d;

    u64 S2[8];
    #pragma unroll
    for (int i = 0; i < 8; i++) S2[i] = 0ull;

    #pragma unroll 1
    for (int t = 0; t < NN; t++) {
        const ulonglong2* kt = kb + t*16;
        ulonglong2 kA = kt[0], kB = kt[1], kC = kt[2], kD = kt[3];
        const ulonglong2* qt = qb + t*16;
        ulonglong2 qA = qt[0], qB = qt[1], qC = qt[2], qD = qt[3];
        float gc = gb[t];
        float vc = vb[t*DD];

        u64 k2[8] = {kA.x, kA.y, kB.x, kB.y, kC.x, kC.y, kD.x, kD.y};
        u64 q2[8] = {qA.x, qA.y, qB.x, qB.y, qC.x, qC.y, qD.x, qD.y};

        // pred = S_row . k   (two packed chains, then sub-lane all-reduce)
        u64 pa = mul2(S2[0], k2[0]);
        pa = fma2(S2[1], k2[1], pa);
        pa = fma2(S2[2], k2[2], pa);
        pa = fma2(S2[3], k2[3], pa);
        u64 pb = mul2(S2[4], k2[4]);
        pb = fma2(S2[5], k2[5], pb);
        pb = fma2(S2[6], k2[6], pb);
        pb = fma2(S2[7], k2[7], pb);
        float2 ua = unp(pa), ub = unp(pb);
        float pred = (ua.x + ua.y) + (ub.x + ub.y);
        pred += __shfl_xor_sync(0xffffffffu, pred, 1);
        pred += __shfl_xor_sync(0xffffffffu, pred, 2);

        float delta = fminf(fmaxf(vc - pred, -5.0f), 5.0f);
        u64 g2 = dup2(gc), dl2 = dup2(delta);

        // S = clip(g*S + delta*k); o = S_new . q  (packed)
        u64 oa, ob;
        S2[0] = upd2(S2[0], k2[0], g2, dl2);  oa = mul2(S2[0], q2[0]);
        S2[1] = upd2(S2[1], k2[1], g2, dl2);  oa = fma2(S2[1], q2[1], oa);
        S2[2] = upd2(S2[2], k2[2], g2, dl2);  oa = fma2(S2[2], q2[2], oa);
        S2[3] = upd2(S2[3], k2[3], g2, dl2);  oa = fma2(S2[3], q2[3], oa);
        S2[4] = upd2(S2[4], k2[4], g2, dl2);  ob = mul2(S2[4], q2[4]);
        S2[5] = upd2(S2[5], k2[5], g2, dl2);  ob = fma2(S2[5], q2[5], ob);
        S2[6] = upd2(S2[6], k2[6], g2, dl2);  ob = fma2(S2[6], q2[6], ob);
        S2[7] = upd2(S2[7], k2[7], g2, dl2);  ob = fma2(S2[7], q2[7], ob);

        float2 oa2 = unp(oa), ob2 = unp(ob);
        float o = (oa2.x + oa2.y) + (ob2.x + ob2.y);
        o += __shfl_xor_sync(0xffffffffu, o, 1);
        o += __shfl_xor_sync(0xffffffffu, o, 2);
        if (sub == 0) op[t*DD] = o;
    }
}

// ---------------- epilogue: 4 rows/warp, packed e-pair matvec ----------------
__global__ void __launch_bounds__(256) post_kernel(
    const float* __restrict__ x, const float* __restrict__ g_post,
    const float* __restrict__ bo, float* __restrict__ out)
{
    const int warp = threadIdx.x >> 5;
    const int lane = threadIdx.x & 31;
    const int row0 = blockIdx.x * 32 + warp * 4;
    __shared__ __align__(16) float sh[8][4][DD];

    float2 gp2 = ((const float2*)g_post)[lane];
    #pragma unroll
    for (int r = 0; r < 4; r++) {
        float2 ov = ((const float2*)(g_o + (row0 + r)*DD))[lane];
        float s = ov.x + ov.y;
        #pragma unroll
        for (int o = 16; o; o >>= 1) s += __shfl_xor_sync(0xffffffffu, s, o);
        float mean = s * (1.0f/64.0f);
        float a0 = ov.x - mean, a1 = ov.y - mean;
        float ss = a0*a0 + a1*a1;
        #pragma unroll
        for (int o = 16; o; o >>= 1) ss += __shfl_xor_sync(0xffffffffu, ss, o);
        float rn = rsqrtf(ss * (1.0f/64.0f) + 1e-8f);
        sh[warp][r][2*lane]   = a0 * rn * gp2.x;
        sh[warp][r][2*lane+1] = a1 * rn * gp2.y;
    }
    __syncwarp();

    u64 aE[4], aO[4];
    #pragma unroll
    for (int r = 0; r < 4; r++) { aE[r] = aO[r] = 0ull; }
    const ulonglong2* Wop = (const ulonglong2*)g_Wop;
    #pragma unroll 4
    for (int e2 = 0; e2 < 32; e2++) {
        ulonglong2 wo = Wop[e2*32 + lane];
        #pragma unroll
        for (int r = 0; r < 4; r++) {
            u64 h2 = ((const u64*)sh[warp][r])[e2];
            aE[r] = fma2(h2, wo.x, aE[r]);
            aO[r] = fma2(h2, wo.y, aO[r]);
        }
    }
    float2 bov = ((const float2*)bo)[lane];
    #pragma unroll
    for (int r = 0; r < 4; r++) {
        float2 e0 = unp(aE[r]), e1 = unp(aO[r]);
        int row = row0 + r;
        float2 xv = ((const float2*)(x + row*DD))[lane];
        ((float2*)(out + row*DD))[lane] =
            make_float2(xv.x + e0.x + e0.y + bov.x,
                        xv.y + e1.x + e1.y + bov.y);
    }
}

// ---------------- launch ----------------
extern "C" void kernel_launch(void* const* d_in, const int* in_sizes, int n_in,
                              void* d_out, int out_size)
{
    const float* x      = (const float*)d_in[0];
    const float* g_norm = (const float*)d_in[1];
    const float* Wq     = (const float*)d_in[2];
    const float* Wk     = (const float*)d_in[3];
    const float* Wv     = (const float*)d_in[4];
    const float* bv     = (const float*)d_in[5];
    const float* Wo     = (const float*)d_in[6];
    const float* bo     = (const float*)d_in[7];
    const float* g_post = (const float*)d_in[8];
    const float* W1     = (const float*)d_in[9];
    const float* b1     = (const float*)d_in[10];
    const float* W2     = (const float*)d_in[11];
    const float* b2     = (const float*)d_in[12];
    float* out          = (float*)d_out;

    init_kernel<<<20, 256>>>(Wq, Wk, Wv, Wo);
    pre_kernel<<<ROWS/32, 256>>>(x, g_norm, bv, W1, b1, W2, b2);
    scan_kernel<<<BB, 256>>>();
    post_kernel<<<ROWS/32, 256>>>(x, g_post, bo, out);
}

// round 7
// speedup vs baseline: 2.7467x; 1.0056x over previous
#include <cuda_runtime.h>
#include <math.h>

#define BB 512
#define NN 120
#define DD 64
#define ROWS (BB*NN)           // 61440
#define NBINS 32

typedef unsigned long long u64;

// ---------------- scratch (static device arrays; no cudaMalloc) ----------------
__device__ float  g_q[ROWS*DD];
__device__ float  g_k[ROWS*DD];
__device__ float  g_v[ROWS*DD];
__device__ float  g_gam[ROWS];
__device__ float  g_o[ROWS*DD];
// packed twiddles: twp[d2*32+f] = (cos(w*f*2d2), cos(w*f*(2d2+1)), sin(...), sin(...))
__device__ float4 g_twp[1024];
// W repacked over e-pairs: P[e2*32+lane] = (W[2e2][2l], W[2e2+1][2l], W[2e2][2l+1], W[2e2+1][2l+1])
__device__ float4 g_Wqp[1024], g_Wkp[1024], g_Wvp[1024], g_Wop[1024];

// ---------------- f32x2 helpers ----------------
__device__ __forceinline__ u64 fma2(u64 a, u64 b, u64 c) {
    u64 d; asm("fma.rn.f32x2 %0,%1,%2,%3;" : "=l"(d) : "l"(a), "l"(b), "l"(c)); return d;
}
__device__ __forceinline__ u64 mul2(u64 a, u64 b) {
    u64 d; asm("mul.rn.f32x2 %0,%1,%2;" : "=l"(d) : "l"(a), "l"(b)); return d;
}
__device__ __forceinline__ u64 dup2(float v) {
    u64 r; asm("mov.b64 %0,{%1,%1};" : "=l"(r) : "f"(v)); return r;
}
__device__ __forceinline__ float2 unp(u64 v) {
    float a, b; asm("mov.b64 {%0,%1},%2;" : "=f"(a), "=f"(b) : "l"(v));
    return make_float2(a, b);
}
// S' = clip(g*S + delta*k, +-10)
__device__ __forceinline__ u64 upd2(u64 S, u64 k, u64 g, u64 delta) {
    u64 r;
    asm("{\n\t"
        ".reg .f32 lo,hi;\n\t"
        ".reg .b64 t;\n\t"
        "mul.rn.f32x2 t, %2, %3;\n\t"
        "fma.rn.f32x2 t, %4, %1, t;\n\t"
        "mov.b64 {lo,hi}, t;\n\t"
        "min.f32 lo, lo, 0f41200000;\n\t"
        "max.f32 lo, lo, 0fC1200000;\n\t"
        "min.f32 hi, hi, 0f41200000;\n\t"
        "max.f32 hi, hi, 0fC1200000;\n\t"
        "mov.b64 %0, {lo,hi};\n\t"
        "}"
        : "=l"(r) : "l"(S), "l"(k), "l"(delta), "l"(g));
    return r;
}

// ---------------- init: packed twiddles + W e-pair repack ----------------
__global__ void init_kernel(const float* __restrict__ Wq, const float* __restrict__ Wk,
                            const float* __restrict__ Wv, const float* __restrict__ Wo) {
    int i = blockIdx.x * blockDim.x + threadIdx.x;
    if (i < 1024) {
        int d2 = i >> 5, f = i & 31;
        int m0 = (f * (2*d2))     & 63;       // exact modular angle reduction
        int m1 = (f * (2*d2 + 1)) & 63;
        const double w = 2.0 * 3.14159265358979323846 / 64.0;
        g_twp[i] = make_float4((float)cos(w*m0), (float)cos(w*m1),
                               (float)sin(w*m0), (float)sin(w*m1));
    } else if (i < 5120) {
        int s = (i - 1024) >> 10, j = (i - 1024) & 1023;
        int e2 = j >> 5, l = j & 31;
        const float* W = (s == 0) ? Wq : (s == 1) ? Wk : (s == 2) ? Wv : Wo;
        float4*      P = (s == 0) ? g_Wqp : (s == 1) ? g_Wkp : (s == 2) ? g_Wvp : g_Wop;
        int a = (2*e2)*DD + 2*l;
        P[j] = make_float4(W[a], W[a+DD], W[a+1], W[a+DD+1]);
    }
}

// matvec pass over one packed matrix: 8 rows, accumulators aE/aO (even/odd e partials)
#define MATVEC_PASS(Wp, aE, aO)                                            \
    {                                                                       \
        _Pragma("unroll")                                                   \
        for (int r = 0; r < 8; r++) { aE[r] = 0ull; aO[r] = 0ull; }        \
        _Pragma("unroll 2")                                                 \
        for (int e4 = 0; e4 < 16; e4++) {                                   \
            ulonglong2 w0 = Wp[(2*e4)*32 + lane];                           \
            ulonglong2 w1 = Wp[(2*e4+1)*32 + lane];                         \
            _Pragma("unroll")                                               \
            for (int r = 0; r < 8; r++) {                                   \
                ulonglong2 hh = ((const ulonglong2*)sh[warp][r])[e4];       \
                aE[r] = fma2(hh.x, w0.x, aE[r]);                            \
                aO[r] = fma2(hh.x, w0.y, aO[r]);                            \
                aE[r] = fma2(hh.y, w1.x, aE[r]);                            \
                aO[r] = fma2(hh.y, w1.y, aO[r]);                            \
            }                                                               \
        }                                                                   \
    }

// ---------------- preprocess: 8 rows/warp, separate passes ----------------
__global__ void __launch_bounds__(256) pre_kernel(
    const float* __restrict__ x,  const float* __restrict__ g_norm,
    const float* __restrict__ bv,
    const float* __restrict__ W1, const float* __restrict__ b1,
    const float* __restrict__ W2, const float* __restrict__ b2)
{
    const int warp = threadIdx.x >> 5;
    const int lane = threadIdx.x & 31;
    const int row0 = blockIdx.x * 64 + warp * 8;
    __shared__ __align__(16) float sh[8][8][DD];
    __shared__ float smag[8][8][NBINS];

    // ---- zc_rms for 8 rows ----
    float2 gv = ((const float2*)g_norm)[lane];
    #pragma unroll
    for (int r = 0; r < 8; r++) {
        float2 xv = ((const float2*)(x + (row0 + r)*DD))[lane];
        float s = xv.x + xv.y;
        #pragma unroll
        for (int o = 16; o; o >>= 1) s += __shfl_xor_sync(0xffffffffu, s, o);
        float mean = s * (1.0f/64.0f);
        float a0 = xv.x - mean, a1 = xv.y - mean;
        float ss = a0*a0 + a1*a1;
        #pragma unroll
        for (int o = 16; o; o >>= 1) ss += __shfl_xor_sync(0xffffffffu, ss, o);
        float rn = rsqrtf(ss * (1.0f/64.0f) + 1e-8f);
        sh[warp][r][2*lane]   = a0 * rn * gv.x;
        sh[warp][r][2*lane+1] = a1 * rn * gv.y;
    }
    __syncwarp();

    u64 aE[8], aO[8];

    // ---- Q pass ----
    MATVEC_PASS(((const ulonglong2*)g_Wqp), aE, aO)
    #pragma unroll
    for (int r = 0; r < 8; r++) {
        float2 e0 = unp(aE[r]), e1 = unp(aO[r]);
        float q0 = e0.x + e0.y, q1 = e1.x + e1.y;
        float qs = q0*q0 + q1*q1;
        #pragma unroll
        for (int o = 16; o; o >>= 1) qs += __shfl_xor_sync(0xffffffffu, qs, o);
        float qr = rsqrtf(qs + 1e-8f);
        ((float2*)(g_q + (row0 + r)*DD))[lane] = make_float2(q0*qr, q1*qr);
    }

    // ---- K pass ----
    MATVEC_PASS(((const ulonglong2*)g_Wkp), aE, aO)
    #pragma unroll
    for (int r = 0; r < 8; r++) {
        float2 e0 = unp(aE[r]), e1 = unp(aO[r]);
        float k0 = e0.x + e0.y, k1 = e1.x + e1.y;
        float ks = k0*k0 + k1*k1;
        #pragma unroll
        for (int o = 16; o; o >>= 1) ks += __shfl_xor_sync(0xffffffffu, ks, o);
        float kr = rsqrtf(ks + 1e-8f);
        ((float2*)(g_k + (row0 + r)*DD))[lane] = make_float2(k0*kr, k1*kr);
    }

    // ---- V pass ----
    MATVEC_PASS(((const ulonglong2*)g_Wvp), aE, aO)
    {
        float2 bvv = ((const float2*)bv)[lane];
        #pragma unroll
        for (int r = 0; r < 8; r++) {
            float2 e0 = unp(aE[r]), e1 = unp(aO[r]);
            ((float2*)(g_v + (row0 + r)*DD))[lane] =
                make_float2(e0.x + e0.y + bvv.x, e1.x + e1.y + bvv.y);
        }
    }

    // ---- DFT pass: bin = lane, packed twiddles ----
    {
        u64 re2[8], im2[8];
        #pragma unroll
        for (int r = 0; r < 8; r++) { re2[r] = 0ull; im2[r] = 0ull; }
        const ulonglong2* Twp = (const ulonglong2*)g_twp;
        #pragma unroll 2
        for (int d4 = 0; d4 < 16; d4++) {
            ulonglong2 t0 = Twp[(2*d4)*32 + lane];     // (cos pair, sin pair)
            ulonglong2 t1 = Twp[(2*d4+1)*32 + lane];
            #pragma unroll
            for (int r = 0; r < 8; r++) {
                ulonglong2 hh = ((const ulonglong2*)sh[warp][r])[d4];
                re2[r] = fma2(hh.x, t0.x, re2[r]);
                im2[r] = fma2(hh.x, t0.y, im2[r]);
                re2[r] = fma2(hh.y, t1.x, re2[r]);
                im2[r] = fma2(hh.y, t1.y, im2[r]);
            }
        }
        #pragma unroll
        for (int r = 0; r < 8; r++) {
            float2 rr = unp(re2[r]), ii = unp(im2[r]);
            float re = rr.x + rr.y, im = ii.x + ii.y;
            smag[warp][r][lane] = sqrtf(re*re + im*im);
        }
    }
    __syncwarp();

    // ---- gate: 8 lanes per row, two half-passes of 4 rows ----
    #pragma unroll
    for (int half = 0; half < 8; half += 4) {
        int r   = half + (lane >> 3);
        int bnd = lane & 7;
        const float* mg = smag[warp][r];
        float en = 0.25f * (mg[4*bnd] + mg[4*bnd+1] + mg[4*bnd+2] + mg[4*bnd+3]);
        float esum = en;
        esum += __shfl_xor_sync(0xffffffffu, esum, 1);
        esum += __shfl_xor_sync(0xffffffffu, esum, 2);
        esum += __shfl_xor_sync(0xffffffffu, esum, 4);
        float eni = en / fmaxf(esum, 1e-8f);
        float z0 = b1[2*bnd], z1 = b1[2*bnd+1];
        int gbase = lane & 24;
        #pragma unroll
        for (int i = 0; i < 8; i++) {
            float ei = __shfl_sync(0xffffffffu, eni, gbase + i);
            z0 = fmaf(ei, W1[i*16 + 2*bnd],     z0);
            z1 = fmaf(ei, W1[i*16 + 2*bnd + 1], z1);
        }
        float s0 = z0 / (1.0f + expf(-z0)) * W2[2*bnd];
        float s1 = z1 / (1.0f + expf(-z1)) * W2[2*bnd+1];
        float hid = s0 + s1;
        hid += __shfl_xor_sync(0xffffffffu, hid, 1);
        hid += __shfl_xor_sync(0xffffffffu, hid, 2);
        hid += __shfl_xor_sync(0xffffffffu, hid, 4);
        if (bnd == 0) {
            float z2 = hid + b2[0];
            g_gam[row0 + r] = 0.5f + 0.49f / (1.0f + expf(-z2));
        }
    }
}

// ---------------- scan: 4 threads/row, packed state, pointer-walk loads ----------------
__global__ void __launch_bounds__(256, 4) scan_kernel() {
    const int b   = blockIdx.x;
    const int d   = threadIdx.x >> 2;
    const int sub = threadIdx.x & 3;

    const ulonglong2* __restrict__ kp = (const ulonglong2*)(g_k + b*NN*DD + sub*16);
    const ulonglong2* __restrict__ qp = (const ulonglong2*)(g_q + b*NN*DD + sub*16);
    const float*  __restrict__ vp = g_v + b*NN*DD + d;
    const float*  __restrict__ gp = g_gam + b*NN;
    float*        __restrict__ op = g_o + b*NN*DD + d;

    u64 S2[8];
    #pragma unroll
    for (int i = 0; i < 8; i++) S2[i] = 0ull;

    #pragma unroll 1
    for (int t = 0; t < NN; t++) {
        ulonglong2 kA = kp[0], kB = kp[1], kC = kp[2], kD = kp[3];
        ulonglong2 qA = qp[0], qB = qp[1], qC = qp[2], qD = qp[3];
        kp += 16; qp += 16;
        float gc = *gp++;
        float vc = *vp; vp += DD;

        u64 k2[8] = {kA.x, kA.y, kB.x, kB.y, kC.x, kC.y, kD.x, kD.y};
        u64 q2[8] = {qA.x, qA.y, qB.x, qB.y, qC.x, qC.y, qD.x, qD.y};

        // pred = S_row . k   (two packed chains, then sub-lane all-reduce)
        u64 pa = mul2(S2[0], k2[0]);
        pa = fma2(S2[1], k2[1], pa);
        pa = fma2(S2[2], k2[2], pa);
        pa = fma2(S2[3], k2[3], pa);
        u64 pb = mul2(S2[4], k2[4]);
        pb = fma2(S2[5], k2[5], pb);
        pb = fma2(S2[6], k2[6], pb);
        pb = fma2(S2[7], k2[7], pb);
        float2 ua = unp(pa), ub = unp(pb);
        float pred = (ua.x + ua.y) + (ub.x + ub.y);
        pred += __shfl_xor_sync(0xffffffffu, pred, 1);
        pred += __shfl_xor_sync(0xffffffffu, pred, 2);

        float delta = fminf(fmaxf(vc - pred, -5.0f), 5.0f);
        u64 g2 = dup2(gc), dl2 = dup2(delta);

        // S = clip(g*S + delta*k); o = S_new . q  (packed)
        u64 oa, ob;
        S2[0] = upd2(S2[0], k2[0], g2, dl2);  oa = mul2(S2[0], q2[0]);
        S2[1] = upd2(S2[1], k2[1], g2, dl2);  oa = fma2(S2[1], q2[1], oa);
        S2[2] = upd2(S2[2], k2[2], g2, dl2);  oa = fma2(S2[2], q2[2], oa);
        S2[3] = upd2(S2[3], k2[3], g2, dl2);  oa = fma2(S2[3], q2[3], oa);
        S2[4] = upd2(S2[4], k2[4], g2, dl2);  ob = mul2(S2[4], q2[4]);
        S2[5] = upd2(S2[5], k2[5], g2, dl2);  ob = fma2(S2[5], q2[5], ob);
        S2[6] = upd2(S2[6], k2[6], g2, dl2);  ob = fma2(S2[6], q2[6], ob);
        S2[7] = upd2(S2[7], k2[7], g2, dl2);  ob = fma2(S2[7], q2[7], ob);

        float2 oa2 = unp(oa), ob2 = unp(ob);
        float o = (oa2.x + oa2.y) + (ob2.x + ob2.y);
        o += __shfl_xor_sync(0xffffffffu, o, 1);
        o += __shfl_xor_sync(0xffffffffu, o, 2);
        if (sub == 0) op[t*DD] = o;
    }
}

// ---------------- epilogue: 8 rows/warp ----------------
__global__ void __launch_bounds__(256) post_kernel(
    const float* __restrict__ x, const float* __restrict__ g_post,
    const float* __restrict__ bo, float* __restrict__ out)
{
    const int warp = threadIdx.x >> 5;
    const int lane = threadIdx.x & 31;
    const int row0 = blockIdx.x * 64 + warp * 8;
    __shared__ __align__(16) float sh[8][8][DD];

    float2 gp2 = ((const float2*)g_post)[lane];
    #pragma unroll
    for (int r = 0; r < 8; r++) {
        float2 ov = ((const float2*)(g_o + (row0 + r)*DD))[lane];
        float s = ov.x + ov.y;
        #pragma unroll
        for (int o = 16; o; o >>= 1) s += __shfl_xor_sync(0xffffffffu, s, o);
        float mean = s * (1.0f/64.0f);
        float a0 = ov.x - mean, a1 = ov.y - mean;
        float ss = a0*a0 + a1*a1;
        #pragma unroll
        for (int o = 16; o; o >>= 1) ss += __shfl_xor_sync(0xffffffffu, ss, o);
        float rn = rsqrtf(ss * (1.0f/64.0f) + 1e-8f);
        sh[warp][r][2*lane]   = a0 * rn * gp2.x;
        sh[warp][r][2*lane+1] = a1 * rn * gp2.y;
    }
    __syncwarp();

    u64 aE[8], aO[8];
    MATVEC_PASS(((const ulonglong2*)g_Wop), aE, aO)

    float2 bov = ((const float2*)bo)[lane];
    #pragma unroll
    for (int r = 0; r < 8; r++) {
        float2 e0 = unp(aE[r]), e1 = unp(aO[r]);
        int row = row0 + r;
        float2 xv = ((const float2*)(x + row*DD))[lane];
        ((float2*)(out + row*DD))[lane] =
            make_float2(xv.x + e0.x + e0.y + bov.x,
                        xv.y + e1.x + e1.y + bov.y);
    }
}

// ---------------- launch ----------------
extern "C" void kernel_launch(void* const* d_in, const int* in_sizes, int n_in,
                              void* d_out, int out_size)
{
    const float* x      = (const float*)d_in[0];
    const float* g_norm = (const float*)d_in[1];
    const float* Wq     = (const float*)d_in[2];
    const float* Wk     = (const float*)d_in[3];
    const float* Wv     = (const float*)d_in[4];
    const float* bv     = (const float*)d_in[5];
    const float* Wo     = (const float*)d_in[6];
    const float* bo     = (const float*)d_in[7];
    const float* g_post = (const float*)d_in[8];
    const float* W1     = (const float*)d_in[9];
    const float* b1     = (const float*)d_in[10];
    const float* W2     = (const float*)d_in[11];
    const float* b2     = (const float*)d_in[12];
    float* out          = (float*)d_out;

    init_kernel<<<20, 256>>>(Wq, Wk, Wv, Wo);
    pre_kernel<<<ROWS/64, 256>>>(x, g_norm, bv, W1, b1, W2, b2);
    scan_kernel<<<BB, 256>>>();
    post_kernel<<<ROWS/64, 256>>>(x, g_post, bo, out);
}